// round 2
// baseline (speedup 1.0000x reference)
#include <cuda_runtime.h>
#include <cuda_bf16.h>
#include <math.h>

#define N_ATOMS 10000
#define E_TILE  32
#define E_STRIDE 36   // E_TILE + 4 pad (keeps float4 alignment, staggers banks)

// Output layout (flattened tuple):
//  l=0: (10000,1,20,4)  base 0        per-atom 80
//  l=1: (10000,3,18,4)  base 800000   per-atom 216
//  l=2: (10000,5,16,4)  base 2960000  per-atom 320
//  l=3: (10000,7,14,4)  base 6160000  per-atom 392

__device__ int g_rowptr[N_ATOMS + 1];

__global__ void rowptr_kernel(const int* __restrict__ I, int nE) {
    int a = blockIdx.x * blockDim.x + threadIdx.x;
    if (a > N_ATOMS) return;
    int lo = 0, hi = nE;
    while (lo < hi) {
        int mid = (lo + hi) >> 1;
        if (I[mid] < a) lo = mid + 1; else hi = mid;
    }
    g_rowptr[a] = lo;
}

__global__ __launch_bounds__(256, 6)
void expand_kernel(const float* __restrict__ R,
                   const int*   __restrict__ J,
                   const int*   __restrict__ species,
                   const float* __restrict__ embed,
                   float*       __restrict__ out)
{
    // transposed staging: feature-major, edge-minor (float4-chunkable over edges)
    __shared__ float radT[20][E_STRIDE];
    __shared__ float angT[16][E_STRIDE];
    __shared__ float spT [4][E_STRIDE];
    __shared__ int s_range[2];

    const int t    = threadIdx.x;
    const int atom = blockIdx.x;

    if (t < 2) s_range[t] = g_rowptr[atom + t];

    // ---- decode this thread's output element ----
    int n, am, outOff;
    {
        int q = t;
        if (q < 20)       { n = q;                          am = 0;             outOff = atom * 80  + q * 4; }
        else if (q < 74)  { int qq = q - 20;  n = qq % 18;  am = 1 + qq / 18;   outOff = 800000  + atom * 216 + qq * 4; }
        else if (q < 154) { int qq = q - 74;  n = qq % 16;  am = 4 + qq / 16;   outOff = 2960000 + atom * 320 + qq * 4; }
        else              { int qq = q - 154; n = qq % 14;  am = 9 + qq / 14;   outOff = 6160000 + atom * 392 + qq * 4; }
    }
    const float* pr = &radT[n][0];
    const float* pa = &angT[am][0];

    __syncthreads();
    const int s0 = s_range[0];
    const int s1 = s_range[1];

    float ax = 0.f, ay = 0.f, az = 0.f, aw = 0.f;

    for (int base = s0; base < s1; base += E_TILE) {
        const int E  = min(E_TILE, s1 - base);
        const int E4 = (E + 3) & ~3;

        if (t < 32) {
            // ---- producer warp 0: radial features ----
            const int lane = t;
            if (lane < E) {
                const int e = base + lane;
                const float x = R[3 * e + 0];
                const float y = R[3 * e + 1];
                const float z = R[3 * e + 2];
                const float r  = sqrtf(x * x + y * y + z * z);
                const float rc = fminf(r, 5.0f);
                const float fc = 0.5f * (__cosf(0.6283185307179586f * rc) + 1.0f);

                float sv1, c1;
                __sincosf(0.6283185307179586f * r, &sv1, &c1);
                // two independent Chebyshev chains (even/odd k)
                const float t2 = 2.0f * (2.0f * c1 * c1 - 1.0f);  // 2*cos(2θ)
                float so_m2 = -sv1;          // s_{-1}
                float so_m1 =  sv1;          // s_1
                float se_m2 = 0.0f;          // s_0
                float se_m1 = 2.0f * c1 * sv1; // s_2
                radT[0][lane] = sv1 * fc;
                radT[1][lane] = se_m1 * fc;
                #pragma unroll
                for (int k = 3; k <= 19; k += 2) {
                    const float so = t2 * so_m1 - so_m2;   // s_k (odd)
                    const float se = t2 * se_m1 - se_m2;   // s_{k+1} (even)
                    so_m2 = so_m1; so_m1 = so;
                    se_m2 = se_m1; se_m1 = se;
                    radT[k - 1][lane] = so * fc;
                    radT[k][lane]     = se * fc;
                }
            } else if (lane < E4) {
                #pragma unroll
                for (int k = 0; k < 20; k++) radT[k][lane] = 0.0f;
            }
        } else if (t < 64) {
            // ---- producer warp 1: angular + species features ----
            const int lane = t - 32;
            if (lane < E) {
                const int e = base + lane;
                const float x = R[3 * e + 0];
                const float y = R[3 * e + 1];
                const float z = R[3 * e + 2];
                const float r   = sqrtf(x * x + y * y + z * z);
                const float inv = 1.0f / (r + 1e-12f);
                const float ux = x * inv, uy = y * inv, uz = z * inv;
                const float x2 = ux * ux, y2 = uy * uy, z2 = uz * uz;

                angT[ 0][lane] = 0.28209479177387814f;
                angT[ 1][lane] = 0.4886025119029199f * uy;
                angT[ 2][lane] = 0.4886025119029199f * uz;
                angT[ 3][lane] = 0.4886025119029199f * ux;
                angT[ 4][lane] = 1.0925484305920792f * ux * uy;
                angT[ 5][lane] = 1.0925484305920792f * uy * uz;
                angT[ 6][lane] = 0.31539156525252005f * (3.0f * z2 - 1.0f);
                angT[ 7][lane] = 1.0925484305920792f * ux * uz;
                angT[ 8][lane] = 0.5462742152960396f * (x2 - y2);
                angT[ 9][lane] = 0.5900435899266435f * uy * (3.0f * x2 - y2);
                angT[10][lane] = 2.890611442640554f * ux * uy * uz;
                angT[11][lane] = 0.4570457994644658f * uy * (5.0f * z2 - 1.0f);
                angT[12][lane] = 0.3731763325901154f * uz * (5.0f * z2 - 3.0f);
                angT[13][lane] = 0.4570457994644658f * ux * (5.0f * z2 - 1.0f);
                angT[14][lane] = 1.445305721320277f  * uz * (x2 - y2);
                angT[15][lane] = 0.5900435899266435f * ux * (x2 - 3.0f * y2);

                const int sp = species[J[e]];
                const float4 sv = *reinterpret_cast<const float4*>(embed + 4 * sp);
                spT[0][lane] = sv.x;
                spT[1][lane] = sv.y;
                spT[2][lane] = sv.z;
                spT[3][lane] = sv.w;
            } else if (lane < E4) {
                #pragma unroll
                for (int k = 0; k < 16; k++) angT[k][lane] = 0.0f;
                #pragma unroll
                for (int k = 0; k < 4; k++)  spT[k][lane] = 0.0f;
            }
        }
        __syncthreads();

        // ---- consumer: 4 edges per iteration, float4 LDS ----
        #pragma unroll 2
        for (int j = 0; j < E4; j += 4) {
            const float4 rv = *reinterpret_cast<const float4*>(pr + j);
            const float4 av = *reinterpret_cast<const float4*>(pa + j);
            const float px = rv.x * av.x;
            const float py = rv.y * av.y;
            const float pz = rv.z * av.z;
            const float pw = rv.w * av.w;
            const float4 sv0 = *reinterpret_cast<const float4*>(&spT[0][j]);
            const float4 sv1 = *reinterpret_cast<const float4*>(&spT[1][j]);
            const float4 sv2 = *reinterpret_cast<const float4*>(&spT[2][j]);
            const float4 sv3 = *reinterpret_cast<const float4*>(&spT[3][j]);
            ax = fmaf(px, sv0.x, fmaf(py, sv0.y, fmaf(pz, sv0.z, fmaf(pw, sv0.w, ax))));
            ay = fmaf(px, sv1.x, fmaf(py, sv1.y, fmaf(pz, sv1.z, fmaf(pw, sv1.w, ay))));
            az = fmaf(px, sv2.x, fmaf(py, sv2.y, fmaf(pz, sv2.z, fmaf(pw, sv2.w, az))));
            aw = fmaf(px, sv3.x, fmaf(py, sv3.y, fmaf(pz, sv3.z, fmaf(pw, sv3.w, aw))));
        }

        if (base + E_TILE < s1) __syncthreads();
    }

    if (t < 252) {
        float4 o; o.x = ax; o.y = ay; o.z = az; o.w = aw;
        *reinterpret_cast<float4*>(out + outOff) = o;
    }
}

extern "C" void kernel_launch(void* const* d_in, const int* in_sizes, int n_in,
                              void* d_out, int out_size)
{
    const float* R       = (const float*)d_in[0];
    const int*   I       = (const int*)  d_in[1];
    const int*   J       = (const int*)  d_in[2];
    const int*   species = (const int*)  d_in[3];
    const float* embed   = (const float*)d_in[4];
    float* out = (float*)d_out;
    const int nE = in_sizes[1];

    rowptr_kernel<<<(N_ATOMS + 1 + 255) / 256, 256>>>(I, nE);
    expand_kernel<<<N_ATOMS, 256>>>(R, J, species, embed, out);
}

// round 3
// speedup vs baseline: 1.1511x; 1.1511x over previous
#include <cuda_runtime.h>
#include <cuda_bf16.h>
#include <math.h>

#define N_ATOMS 10000
#define E_TILE  32
#define STR     42     // floats per edge row: 20 rad | 16 ang | 4 sp | 2 pad (even -> 8B align; 2-way max bank conflict on stores)

// Output layout (flattened tuple):
//  l=0: (10000,1,20,4)  base 0        per-atom 80
//  l=1: (10000,3,18,4)  base 800000   per-atom 216
//  l=2: (10000,5,16,4)  base 2960000  per-atom 320
//  l=3: (10000,7,14,4)  base 6160000  per-atom 392

__device__ int g_rowptr[N_ATOMS + 1];

__global__ void rowptr_kernel(const int* __restrict__ I, int nE) {
    int a = blockIdx.x * blockDim.x + threadIdx.x;
    if (a > N_ATOMS) return;
    int lo = 0, hi = nE;
    while (lo < hi) {
        int mid = (lo + hi) >> 1;
        if (I[mid] < a) lo = mid + 1; else hi = mid;
    }
    g_rowptr[a] = lo;
}

__device__ __forceinline__ unsigned long long pack2(float a, float b) {
    unsigned long long r;
    asm("mov.b64 %0, {%1, %2};" : "=l"(r) : "f"(a), "f"(b));
    return r;
}
__device__ __forceinline__ void unpack2(unsigned long long v, float& a, float& b) {
    asm("mov.b64 {%0, %1}, %2;" : "=f"(a), "=f"(b) : "l"(v));
}
__device__ __forceinline__ unsigned long long fma2(unsigned long long a, unsigned long long b, unsigned long long c) {
    unsigned long long d;
    asm("fma.rn.f32x2 %0, %1, %2, %3;" : "=l"(d) : "l"(a), "l"(b), "l"(c));
    return d;
}

__global__ __launch_bounds__(128, 8)
void expand_kernel(const float* __restrict__ R,
                   const int*   __restrict__ J,
                   const int*   __restrict__ species,
                   const float* __restrict__ embed,
                   float*       __restrict__ out)
{
    __shared__ float sh[4][E_TILE * STR];

    const int warp = threadIdx.x >> 5;
    const int lane = threadIdx.x & 31;
    const int atom = blockIdx.x * 4 + warp;
    float* tile = sh[warp];

    const int s0 = g_rowptr[atom];
    const int s1 = g_rowptr[atom + 1];

    // ---- per-lane output mapping: q = lane*8 + k, pairs (q even, q+1) share m, consecutive n ----
    int radOff[4], angOff[4];
    #pragma unroll
    for (int p = 0; p < 4; p++) {
        int q = lane * 8 + 2 * p;
        if (q > 250) q = 250;             // lane 31 dead slots: safe duplicate, never stored
        int n, m;
        if (q < 20)       { n = q;                          m = 0; }
        else if (q < 74)  { int qq = q - 20;  n = qq % 18;  m = 1 + qq / 18; }
        else if (q < 154) { int qq = q - 74;  n = qq % 16;  m = 4 + qq / 16; }
        else              { int qq = q - 154; n = qq % 14;  m = 9 + qq / 14; }
        radOff[p] = n;          // even -> 8B-aligned float2
        angOff[p] = 20 + m;
    }

    unsigned long long a01[8], a23[8];
    #pragma unroll
    for (int k = 0; k < 8; k++) { a01[k] = 0ULL; a23[k] = 0ULL; }

    for (int base = s0; base < s1; base += E_TILE) {
        const int E = min(E_TILE, s1 - base);

        // ---- producer: one edge per lane ----
        if (lane < E) {
            const int e = base + lane;
            const float x = R[3 * e + 0];
            const float y = R[3 * e + 1];
            const float z = R[3 * e + 2];
            const float d    = x * x + y * y + z * z;
            const float rinv = rsqrtf(d);
            const float r    = d * rinv;
            const float ux = x * rinv, uy = y * rinv, uz = z * rinv;

            float sv1, c1;
            __sincosf(0.6283185307179586f * r, &sv1, &c1);
            // cutoff: rc=min(r,5) -> cos(pi*rc/5) = c1 for r<=5, -1 for r>5 -> fc=0
            const float fc = (r <= 5.0f) ? (0.5f * (c1 + 1.0f)) : 0.0f;

            float* row = tile + lane * STR;

            // radial sin(k*theta)*fc via dual (odd/even) Chebyshev chains, stored as pairs
            const float t2 = 2.0f * (2.0f * c1 * c1 - 1.0f);   // 2*cos(2theta)
            float so_m2 = -sv1;                 // s_{-1}
            float so_m1 =  sv1;                 // s_1
            float se_m2 = 0.0f;                 // s_0
            float se_m1 = 2.0f * c1 * sv1;      // s_2
            *reinterpret_cast<float2*>(row + 0) = make_float2(sv1 * fc, se_m1 * fc);
            #pragma unroll
            for (int k = 3; k <= 19; k += 2) {
                const float so = t2 * so_m1 - so_m2;    // s_k   (odd)
                const float se = t2 * se_m1 - se_m2;    // s_{k+1} (even)
                so_m2 = so_m1; so_m1 = so;
                se_m2 = se_m1; se_m1 = se;
                *reinterpret_cast<float2*>(row + (k - 1)) = make_float2(so * fc, se * fc);
            }

            // angular (real SH, reference order), pairwise stores
            const float x2 = ux * ux, y2 = uy * uy, z2 = uz * uz;
            *reinterpret_cast<float2*>(row + 20) = make_float2(0.28209479177387814f,
                                                               0.4886025119029199f * uy);
            *reinterpret_cast<float2*>(row + 22) = make_float2(0.4886025119029199f * uz,
                                                               0.4886025119029199f * ux);
            *reinterpret_cast<float2*>(row + 24) = make_float2(1.0925484305920792f * ux * uy,
                                                               1.0925484305920792f * uy * uz);
            *reinterpret_cast<float2*>(row + 26) = make_float2(0.31539156525252005f * (3.0f * z2 - 1.0f),
                                                               1.0925484305920792f * ux * uz);
            *reinterpret_cast<float2*>(row + 28) = make_float2(0.5462742152960396f * (x2 - y2),
                                                               0.5900435899266435f * uy * (3.0f * x2 - y2));
            *reinterpret_cast<float2*>(row + 30) = make_float2(2.890611442640554f * ux * uy * uz,
                                                               0.4570457994644658f * uy * (5.0f * z2 - 1.0f));
            *reinterpret_cast<float2*>(row + 32) = make_float2(0.3731763325901154f * uz * (5.0f * z2 - 3.0f),
                                                               0.4570457994644658f * ux * (5.0f * z2 - 1.0f));
            *reinterpret_cast<float2*>(row + 34) = make_float2(1.445305721320277f  * uz * (x2 - y2),
                                                               0.5900435899266435f * ux * (x2 - 3.0f * y2));

            const int sp = species[J[e]];
            const float4 sv = *reinterpret_cast<const float4*>(embed + 4 * sp);
            *reinterpret_cast<float2*>(row + 36) = make_float2(sv.x, sv.y);
            *reinterpret_cast<float2*>(row + 38) = make_float2(sv.z, sv.w);
        }
        __syncwarp();

        // ---- consumer: whole warp sweeps edges; each lane updates its 32 output scalars ----
        #pragma unroll 2
        for (int e = 0; e < E; e++) {
            const float* row = tile + e * STR;
            const unsigned long long sp01 = *reinterpret_cast<const unsigned long long*>(row + 36);
            const unsigned long long sp23 = *reinterpret_cast<const unsigned long long*>(row + 38);
            #pragma unroll
            for (int p = 0; p < 4; p++) {
                const float  a  = row[angOff[p]];
                const float2 rr = *reinterpret_cast<const float2*>(row + radOff[p]);
                const float p0 = rr.x * a;
                const float p1 = rr.y * a;
                const unsigned long long pp0 = pack2(p0, p0);
                const unsigned long long pp1 = pack2(p1, p1);
                a01[2 * p]     = fma2(pp0, sp01, a01[2 * p]);
                a23[2 * p]     = fma2(pp0, sp23, a23[2 * p]);
                a01[2 * p + 1] = fma2(pp1, sp01, a01[2 * p + 1]);
                a23[2 * p + 1] = fma2(pp1, sp23, a23[2 * p + 1]);
            }
        }
        __syncwarp();
    }

    // ---- epilogue: one float4 store per owned (m,n) ----
    #pragma unroll
    for (int k = 0; k < 8; k++) {
        const int q = lane * 8 + k;
        if (q >= 252) break;
        int off;
        if (q < 20)       off = atom * 80  + q * 4;
        else if (q < 74)  off = 800000  + atom * 216 + (q - 20)  * 4;
        else if (q < 154) off = 2960000 + atom * 320 + (q - 74)  * 4;
        else              off = 6160000 + atom * 392 + (q - 154) * 4;
        float4 o;
        unpack2(a01[k], o.x, o.y);
        unpack2(a23[k], o.z, o.w);
        *reinterpret_cast<float4*>(out + off) = o;
    }
}

extern "C" void kernel_launch(void* const* d_in, const int* in_sizes, int n_in,
                              void* d_out, int out_size)
{
    const float* R       = (const float*)d_in[0];
    const int*   I       = (const int*)  d_in[1];
    const int*   J       = (const int*)  d_in[2];
    const int*   species = (const int*)  d_in[3];
    const float* embed   = (const float*)d_in[4];
    float* out = (float*)d_out;
    const int nE = in_sizes[1];

    rowptr_kernel<<<(N_ATOMS + 1 + 255) / 256, 256>>>(I, nE);
    expand_kernel<<<N_ATOMS / 4, 128>>>(R, J, species, embed, out);
}